// round 11
// baseline (speedup 1.0000x reference)
#include <cuda_runtime.h>
#include <cstdint>

#define ROW_LEN   16384
#define KSEL      64
#define MAXROWS   8192
#define UNITS_PER_ROW 16          // 2 CTAs/row x 8 warps
#define SEG       48              // candidate slots per warp-unit
#define T0F       2.30f           // filter threshold; exact fallback covers any input
#define DCAP      256             // dense candidate capacity (8 regs/lane)
#define DREG      8

// Global scratch (static — no allocations).
__device__ uint32_t g_cnt[MAXROWS * UNITS_PER_ROW];
__device__ uint32_t g_seg[MAXROWS * UNITS_PER_ROW * SEG];   // ~25 MB (L2-resident)
__device__ uint32_t g_done[MAXROWS];                        // zero-init; self-resetting

// Monotonic transform: descending float order == descending uint order.
__device__ __forceinline__ uint32_t fwd_xform(uint32_t u) {
    return (u & 0x80000000u) ? ~u : (u | 0x80000000u);
}
__device__ __forceinline__ float inv_xform(uint32_t u) {
    return __uint_as_float((u & 0x80000000u) ? (u ^ 0x80000000u) : ~u);
}

// ---------------------------------------------------------------------------
// Fused kernel: streaming filter (proven ~6.3 TB/s body, unchanged) + inline
// per-row warp selection run by the second-finishing CTA of each row.
// ---------------------------------------------------------------------------
__global__ void __launch_bounds__(256, 6)
topk_fused_kernel(const float* __restrict__ x, float* __restrict__ out) {
    __shared__ uint32_t wcnt[8];
    __shared__ uint32_t stage[8 * SEG];   // reused as dense[256] + sel[64] in selection
    __shared__ uint32_t is_last;

    const int cta  = blockIdx.x;
    const int row  = cta >> 1;
    const int tid  = threadIdx.x;
    const int wid  = tid >> 5;
    const int lane = tid & 31;

    if (tid < 8) wcnt[tid] = 0;
    __syncthreads();

    // ---- Phase 1: streaming filter over this CTA's half-row ----
    const float4* src4 = reinterpret_cast<const float4*>(x) + (size_t)cta * 2048;

    #pragma unroll
    for (int ot = 0; ot < 2; ++ot) {
        float4 v[4];
        #pragma unroll
        for (int j = 0; j < 4; ++j)
            v[j] = src4[(ot * 4 + j) * 256 + tid];
        #pragma unroll
        for (int j = 0; j < 4; ++j) {
            float f[4] = {v[j].x, v[j].y, v[j].z, v[j].w};
            #pragma unroll
            for (int c = 0; c < 4; ++c) {
                if (f[c] > T0F) {
                    uint32_t pos = atomicAdd(&wcnt[wid], 1u);
                    if (pos < SEG) stage[wid * SEG + pos] = __float_as_uint(f[c]);
                }
            }
        }
    }
    __syncthreads();

    const uint32_t unitbase = (uint32_t)cta * 8;
    if (tid < 8) g_cnt[unitbase + tid] = wcnt[tid];
    for (int i = tid; i < 8 * SEG; i += 256) {
        int w = i / SEG, s = i - w * SEG;
        uint32_t c = wcnt[w];
        if ((uint32_t)s < (c < SEG ? c : (uint32_t)SEG))
            g_seg[(unitbase + w) * SEG + s] = stage[i];
    }

    // ---- Handshake: second CTA of the row performs selection ----
    __threadfence();
    if (tid == 0) {
        uint32_t old = atomicAdd(&g_done[row], 1u);
        is_last = (old == 1u);
        if (old == 1u) g_done[row] = 0u;   // reset for next graph replay
    }
    __syncthreads();
    if (!is_last || wid != 0) return;      // only warp 0 of the last CTA
    __threadfence();                       // acquire side of the handshake

    // ---- Phase 2: warp-wide exact select (round-10-proven logic) ----
    uint32_t* dense = stage;               // 256 words
    uint32_t* sel   = stage + DCAP;        // 64 words

    uint32_t myc = (lane < UNITS_PER_ROW) ? g_cnt[row * UNITS_PER_ROW + lane] : 0u;
    const uint32_t total = __reduce_add_sync(0xFFFFFFFFu, myc);
    const bool ovf = __any_sync(0xFFFFFFFFu, myc > SEG);
    const bool fb  = ovf || (total < KSEL) || (total > DCAP);

    uint32_t T;          // transformed bit pattern of the 64th largest
    uint32_t total_gt;   // # strictly greater than T (<= 63)

    if (!fb) {
        // Exclusive prefix of unit counts.
        uint32_t off = myc;
        #pragma unroll
        for (int d = 1; d < 32; d <<= 1) {
            uint32_t v = __shfl_up_sync(0xFFFFFFFFu, off, d);
            if (lane >= d) off += v;
        }
        const uint32_t excl_me = off - myc;

        #pragma unroll
        for (int r = 0; r < DCAP / 32; ++r) dense[lane + 32 * r] = 0;
        __syncwarp();

        const int unit = lane >> 1;
        const int sub  = lane & 1;
        const uint32_t cu   = __shfl_sync(0xFFFFFFFFu, myc, unit);
        const uint32_t base = __shfl_sync(0xFFFFFFFFu, excl_me, unit);
        const uint32_t* segp = g_seg + ((size_t)row * UNITS_PER_ROW + unit) * SEG;

        uint32_t land = 0xFFFFFFFFu, lor = 0;  // AND/OR over real candidates
        for (uint32_t j = sub; j < cu; j += 2) {
            uint32_t v = segp[j] | 0x80000000u; // transformed (all positive)
            dense[base + j] = v;
            land &= v; lor |= v;
        }
        const uint32_t and_all = __reduce_and_sync(0xFFFFFFFFu, land);
        const uint32_t or_all  = __reduce_or_sync(0xFFFFFFFFu, lor);
        __syncwarp();

        uint32_t t[DREG];
        #pragma unroll
        for (int r = 0; r < DREG; ++r) t[r] = dense[lane + 32 * r];

        // Bitwise search, skipping the common prefix.
        const uint32_t diff = and_all ^ or_all;
        if (diff == 0) {
            T = and_all;
        } else {
            const int hb = 31 - __clz(diff);
            T = (hb == 31) ? 0u : (and_all & ~((2u << hb) - 1u));
            #pragma unroll 1
            for (int b = hb; b >= 0; --b) {
                const uint32_t c = T | (1u << b);
                int loc = 0;
                #pragma unroll
                for (int r = 0; r < DREG; ++r) loc += (int)(t[r] >= c);
                if (__reduce_add_sync(0xFFFFFFFFu, loc) >= KSEL) T = c;
            }
        }

        // Compact strict survivors via shfl exclusive scan.
        int cg = 0;
        #pragma unroll
        for (int r = 0; r < DREG; ++r) cg += (int)(t[r] > T);
        int so = cg;
        #pragma unroll
        for (int d = 1; d < 32; d <<= 1) {
            int v = __shfl_up_sync(0xFFFFFFFFu, so, d);
            if (lane >= d) so += v;
        }
        total_gt = (uint32_t)__shfl_sync(0xFFFFFFFFu, so, 31);
        so -= cg;  // exclusive
        #pragma unroll
        for (int r = 0; r < DREG; ++r)
            if (t[r] > T) sel[so++] = t[r];
        __syncwarp();
    } else {
        // Exact fallback over the full row (any input distribution).
        const uint32_t* src = reinterpret_cast<const uint32_t*>(x) + (size_t)row * ROW_LEN;
        T = 0;
        #pragma unroll 1
        for (int b = 31; b >= 0; --b) {
            const uint32_t c = T | (1u << b);
            int loc = 0;
            for (int i = lane; i < ROW_LEN; i += 32)
                loc += (int)(fwd_xform(src[i]) >= c);
            if (__reduce_add_sync(0xFFFFFFFFu, loc) >= KSEL) T = c;
        }
        uint32_t nsel = 0;
        for (int i0 = 0; i0 < ROW_LEN; i0 += 32) {
            uint32_t u = fwd_xform(src[i0 + lane]);
            bool p = u > T;
            unsigned m = __ballot_sync(0xFFFFFFFFu, p);
            if (p) {
                uint32_t pos = nsel + (uint32_t)__popc(m & ((1u << lane) - 1u));
                sel[pos] = u;   // < 64 total by construction
            }
            nsel += (uint32_t)__popc(m);
        }
        total_gt = nsel;
        __syncwarp();
    }

    // ---- Tie fill + rank-sort 64 winners (descending), write ----
    #pragma unroll
    for (int r = 0; r < 2; ++r) {
        int i = lane + 32 * r;
        if ((uint32_t)i >= total_gt) sel[i] = T;
    }
    __syncwarp();

    #pragma unroll
    for (int r = 0; r < 2; ++r) {
        const int i = lane + 32 * r;
        const uint32_t v = sel[i];
        int rank = 0;
        #pragma unroll
        for (int j = 0; j < KSEL; ++j) {
            uint32_t u = sel[j];
            rank += (int)((u > v) | ((u == v) & (j < i)));
        }
        out[(size_t)row * KSEL + rank] = inv_xform(v);
    }
}

extern "C" void kernel_launch(void* const* d_in, const int* in_sizes, int n_in,
                              void* d_out, int out_size) {
    const float* x = (const float*)d_in[0];
    float* out = (float*)d_out;
    int rows = in_sizes[0] / ROW_LEN;
    if (rows > MAXROWS) rows = MAXROWS;
    topk_fused_kernel<<<rows * 2, 256>>>(x, out);
}

// round 12
// speedup vs baseline: 1.0662x; 1.0662x over previous
#include <cuda_runtime.h>
#include <cstdint>

#define ROW_LEN   16384
#define KSEL      64
#define MAXROWS   8192
#define UNITS_PER_ROW 16          // 2 CTAs/row x 8 warps in K1
#define SEG       48              // candidate slots per warp-unit
#define T0F       2.30f           // filter threshold; exact fallback covers any input
#define K2_WARPS  8
#define DCAP      256             // dense candidate capacity (8 regs/lane)
#define DREG      8

// Global scratch (static — no allocations).
__device__ uint32_t g_cnt[MAXROWS * UNITS_PER_ROW];
__device__ uint32_t g_seg[MAXROWS * UNITS_PER_ROW * SEG];   // ~25 MB (L2-resident)

// Monotonic transform: descending float order == descending uint order.
__device__ __forceinline__ uint32_t fwd_xform(uint32_t u) {
    return (u & 0x80000000u) ? ~u : (u | 0x80000000u);
}
__device__ __forceinline__ float inv_xform(uint32_t u) {
    return __uint_as_float((u & 0x80000000u) ? (u ^ 0x80000000u) : ~u);
}

// ---------------------------------------------------------------------------
// K1: pure streaming filter. One CTA per half-row (8192 elems, 32/thread).
// All 8 LDG.128 front-batched for 2x MLP; 5 CTAs/SM for register headroom.
// ---------------------------------------------------------------------------
__global__ void __launch_bounds__(256, 5)
filter_kernel(const float* __restrict__ x) {
    __shared__ uint32_t wcnt[8];
    __shared__ uint32_t stage[8 * SEG];

    const int cta  = blockIdx.x;
    const int tid  = threadIdx.x;
    const int wid  = tid >> 5;

    if (tid < 8) wcnt[tid] = 0;
    __syncthreads();

    const float4* src4 = reinterpret_cast<const float4*>(x) + (size_t)cta * 2048;

    // One deep front batch: 8 x LDG.128 in flight before any consumption.
    float4 v[8];
    #pragma unroll
    for (int j = 0; j < 8; ++j)
        v[j] = src4[j * 256 + tid];

    #pragma unroll
    for (int j = 0; j < 8; ++j) {
        float f[4] = {v[j].x, v[j].y, v[j].z, v[j].w};
        #pragma unroll
        for (int c = 0; c < 4; ++c) {
            if (f[c] > T0F) {
                uint32_t pos = atomicAdd(&wcnt[wid], 1u);
                if (pos < SEG) stage[wid * SEG + pos] = __float_as_uint(f[c]);
            }
        }
    }
    __syncthreads();

    const uint32_t unitbase = (uint32_t)cta * 8;
    if (tid < 8) g_cnt[unitbase + tid] = wcnt[tid];
    for (int i = tid; i < 8 * SEG; i += 256) {
        int w = i / SEG, s = i - w * SEG;
        uint32_t c = wcnt[w];
        if ((uint32_t)s < (c < SEG ? c : (uint32_t)SEG))
            g_seg[(unitbase + w) * SEG + s] = stage[i];
    }
}

// ---------------------------------------------------------------------------
// K2: one WARP per row. Dense-compacted candidates (8 regs/lane) + common-
// prefix-skipped exact bitwise select. Proven at ~22 us. Unchanged.
// ---------------------------------------------------------------------------
__global__ void __launch_bounds__(32 * K2_WARPS)
select_kernel(const float* __restrict__ x, float* __restrict__ out) {
    __shared__ uint32_t dense_all[K2_WARPS][DCAP];
    __shared__ uint32_t sel_all[K2_WARPS][KSEL];
    __shared__ uint32_t fcnt[K2_WARPS];

    const int widx = threadIdx.x >> 5;
    const int lane = threadIdx.x & 31;
    const int row  = blockIdx.x * K2_WARPS + widx;

    uint32_t* dense = dense_all[widx];
    uint32_t* sel   = sel_all[widx];

    uint32_t myc = (lane < UNITS_PER_ROW) ? g_cnt[row * UNITS_PER_ROW + lane] : 0u;
    const uint32_t total = __reduce_add_sync(0xFFFFFFFFu, myc);
    const bool ovf = __any_sync(0xFFFFFFFFu, myc > SEG);
    const bool fb  = ovf || (total < KSEL) || (total > DCAP);

    uint32_t T;          // transformed bit pattern of the 64th largest
    uint32_t total_gt;   // # strictly greater than T (<= 63)

    if (!fb) {
        // Exclusive prefix of unit counts (lanes >=16 contribute 0).
        uint32_t off = myc;
        #pragma unroll
        for (int d = 1; d < 32; d <<= 1) {
            uint32_t v = __shfl_up_sync(0xFFFFFFFFu, off, d);
            if (lane >= d) off += v;
        }
        const uint32_t excl_me = off - myc;

        #pragma unroll
        for (int r = 0; r < DCAP / 32; ++r) dense[lane + 32 * r] = 0;
        __syncwarp();

        const int unit = lane >> 1;
        const int sub  = lane & 1;
        const uint32_t cu   = __shfl_sync(0xFFFFFFFFu, myc, unit);
        const uint32_t base = __shfl_sync(0xFFFFFFFFu, excl_me, unit);
        const uint32_t* segp = g_seg + ((size_t)row * UNITS_PER_ROW + unit) * SEG;

        uint32_t land = 0xFFFFFFFFu, lor = 0;  // AND/OR over real candidates
        for (uint32_t j = sub; j < cu; j += 2) {
            uint32_t v = segp[j] | 0x80000000u;   // transformed (all positive)
            dense[base + j] = v;
            land &= v; lor |= v;
        }
        const uint32_t and_all = __reduce_and_sync(0xFFFFFFFFu, land);
        const uint32_t or_all  = __reduce_or_sync(0xFFFFFFFFu, lor);
        __syncwarp();

        uint32_t t[DREG];
        #pragma unroll
        for (int r = 0; r < DREG; ++r) t[r] = dense[lane + 32 * r];

        // Bitwise search, skipping the common prefix.
        const uint32_t diff = and_all ^ or_all;
        if (diff == 0) {
            T = and_all;
        } else {
            const int hb = 31 - __clz(diff);
            T = (hb == 31) ? 0u : (and_all & ~((2u << hb) - 1u));
            #pragma unroll 1
            for (int b = hb; b >= 0; --b) {
                const uint32_t c = T | (1u << b);
                int loc = 0;
                #pragma unroll
                for (int r = 0; r < DREG; ++r) loc += (int)(t[r] >= c);
                if (__reduce_add_sync(0xFFFFFFFFu, loc) >= KSEL) T = c;
            }
        }

        // Compact strict survivors via shfl exclusive scan.
        int cg = 0;
        #pragma unroll
        for (int r = 0; r < DREG; ++r) cg += (int)(t[r] > T);
        int so = cg;
        #pragma unroll
        for (int d = 1; d < 32; d <<= 1) {
            int v = __shfl_up_sync(0xFFFFFFFFu, so, d);
            if (lane >= d) so += v;
        }
        total_gt = (uint32_t)__shfl_sync(0xFFFFFFFFu, so, 31);
        so -= cg;  // exclusive
        #pragma unroll
        for (int r = 0; r < DREG; ++r)
            if (t[r] > T) sel[so++] = t[r];
        __syncwarp();
    } else {
        // Exact fallback over the full row (any input distribution).
        const uint32_t* src = reinterpret_cast<const uint32_t*>(x) + (size_t)row * ROW_LEN;
        T = 0;
        #pragma unroll 1
        for (int b = 31; b >= 0; --b) {
            const uint32_t c = T | (1u << b);
            int loc = 0;
            for (int i = lane; i < ROW_LEN; i += 32)
                loc += (int)(fwd_xform(src[i]) >= c);
            if (__reduce_add_sync(0xFFFFFFFFu, loc) >= KSEL) T = c;
        }
        if (lane == 0) fcnt[widx] = 0;
        __syncwarp();
        for (int i = lane; i < ROW_LEN; i += 32) {
            uint32_t u = fwd_xform(src[i]);
            if (u > T) sel[atomicAdd(&fcnt[widx], 1u)] = u;  // < 64 by construction
        }
        __syncwarp();
        total_gt = fcnt[widx];
    }

    // Tie fill + rank-sort 64 winners (descending), write.
    #pragma unroll
    for (int r = 0; r < 2; ++r) {
        int i = lane + 32 * r;
        if ((uint32_t)i >= total_gt) sel[i] = T;
    }
    __syncwarp();

    #pragma unroll
    for (int r = 0; r < 2; ++r) {
        const int i = lane + 32 * r;
        const uint32_t v = sel[i];
        int rank = 0;
        #pragma unroll
        for (int j = 0; j < KSEL; ++j) {
            uint32_t u = sel[j];
            rank += (int)((u > v) | ((u == v) & (j < i)));
        }
        out[(size_t)row * KSEL + rank] = inv_xform(v);
    }
}

extern "C" void kernel_launch(void* const* d_in, const int* in_sizes, int n_in,
                              void* d_out, int out_size) {
    const float* x = (const float*)d_in[0];
    float* out = (float*)d_out;
    int rows = in_sizes[0] / ROW_LEN;
    if (rows > MAXROWS) rows = MAXROWS;
    filter_kernel<<<rows * 2, 256>>>(x);
    select_kernel<<<rows / K2_WARPS, 32 * K2_WARPS>>>(x, out);
}

// round 14
// speedup vs baseline: 1.0876x; 1.0201x over previous
#include <cuda_runtime.h>
#include <cstdint>

#define ROW_LEN   16384
#define KSEL      64
#define MAXROWS   8192
#define UNITS_PER_ROW 16          // 2 CTAs/row x 8 warps in K1
#define SEG       48              // candidate slots per warp-unit
#define T0F       2.30f           // filter threshold; exact fallback covers any input
#define K2_WARPS  8
#define DCAP      256             // dense candidate capacity (8 regs/lane)
#define DREG      8

// Global scratch (static — no allocations).
__device__ uint32_t g_cnt[MAXROWS * UNITS_PER_ROW];
__device__ uint32_t g_seg[MAXROWS * UNITS_PER_ROW * SEG];   // ~25 MB (L2-resident)

// Monotonic transform: descending float order == descending uint order.
__device__ __forceinline__ uint32_t fwd_xform(uint32_t u) {
    return (u & 0x80000000u) ? ~u : (u | 0x80000000u);
}
__device__ __forceinline__ float inv_xform(uint32_t u) {
    return __uint_as_float((u & 0x80000000u) ? (u ^ 0x80000000u) : ~u);
}

// ---------------------------------------------------------------------------
// K1: pure streaming filter, fully warp-independent. One CTA per half-row;
// each warp owns one 1024-element unit (256 float4s, 8 per lane). Ballot-scan
// push straight to gmem: no atomics, no shared memory, no barriers.
// ---------------------------------------------------------------------------
__global__ void __launch_bounds__(256, 5)
filter_kernel(const float* __restrict__ x) {
    const int cta  = blockIdx.x;
    const int tid  = threadIdx.x;
    const int wid  = tid >> 5;
    const int lane = tid & 31;

    const uint32_t unit = (uint32_t)cta * 8 + wid;
    uint32_t* seg = g_seg + (size_t)unit * SEG;
    const uint32_t lmask = (1u << lane) - 1u;

    // This warp's 256 float4s: lane loads j*32 + lane for j = 0..7.
    const float4* src4 = reinterpret_cast<const float4*>(x)
                       + (size_t)cta * 2048 + wid * 256 + lane;

    // One front batch: all 8 LDG.128 in flight before any consumption.
    float4 v[8];
    #pragma unroll
    for (int j = 0; j < 8; ++j)
        v[j] = __ldcs(&src4[j * 32]);

    uint32_t cnt = 0;
    #pragma unroll
    for (int j = 0; j < 8; ++j) {
        float f[4] = {v[j].x, v[j].y, v[j].z, v[j].w};
        #pragma unroll
        for (int c = 0; c < 4; ++c) {
            bool p = f[c] > T0F;
            unsigned m = __ballot_sync(0xFFFFFFFFu, p);
            uint32_t pos = cnt + (uint32_t)__popc(m & lmask);
            if (p && pos < SEG) seg[pos] = __float_as_uint(f[c]);
            cnt += (uint32_t)__popc(m);
        }
    }

    if (lane == 0) g_cnt[unit] = cnt;   // cnt > SEG routes K2 to exact fallback
}

// ---------------------------------------------------------------------------
// K2: one WARP per row. Dense-compacted candidates (8 regs/lane) + common-
// prefix-skipped exact bitwise select. Proven at ~22 us. Unchanged.
// ---------------------------------------------------------------------------
__global__ void __launch_bounds__(32 * K2_WARPS)
select_kernel(const float* __restrict__ x, float* __restrict__ out) {
    __shared__ uint32_t dense_all[K2_WARPS][DCAP];
    __shared__ uint32_t sel_all[K2_WARPS][KSEL];
    __shared__ uint32_t fcnt[K2_WARPS];

    const int widx = threadIdx.x >> 5;
    const int lane = threadIdx.x & 31;
    const int row  = blockIdx.x * K2_WARPS + widx;

    uint32_t* dense = dense_all[widx];
    uint32_t* sel   = sel_all[widx];

    uint32_t myc = (lane < UNITS_PER_ROW) ? g_cnt[row * UNITS_PER_ROW + lane] : 0u;
    const uint32_t total = __reduce_add_sync(0xFFFFFFFFu, myc);
    const bool ovf = __any_sync(0xFFFFFFFFu, myc > SEG);
    const bool fb  = ovf || (total < KSEL) || (total > DCAP);

    uint32_t T;          // transformed bit pattern of the 64th largest
    uint32_t total_gt;   // # strictly greater than T (<= 63)

    if (!fb) {
        // Exclusive prefix of unit counts (lanes >=16 contribute 0).
        uint32_t off = myc;
        #pragma unroll
        for (int d = 1; d < 32; d <<= 1) {
            uint32_t v = __shfl_up_sync(0xFFFFFFFFu, off, d);
            if (lane >= d) off += v;
        }
        const uint32_t excl_me = off - myc;

        #pragma unroll
        for (int r = 0; r < DCAP / 32; ++r) dense[lane + 32 * r] = 0;
        __syncwarp();

        const int unit = lane >> 1;
        const int sub  = lane & 1;
        const uint32_t cu   = __shfl_sync(0xFFFFFFFFu, myc, unit);
        const uint32_t base = __shfl_sync(0xFFFFFFFFu, excl_me, unit);
        const uint32_t* segp = g_seg + ((size_t)row * UNITS_PER_ROW + unit) * SEG;

        uint32_t land = 0xFFFFFFFFu, lor = 0;  // AND/OR over real candidates
        for (uint32_t j = sub; j < cu; j += 2) {
            uint32_t v = segp[j] | 0x80000000u;   // transformed (all positive)
            dense[base + j] = v;
            land &= v; lor |= v;
        }
        const uint32_t and_all = __reduce_and_sync(0xFFFFFFFFu, land);
        const uint32_t or_all  = __reduce_or_sync(0xFFFFFFFFu, lor);
        __syncwarp();

        uint32_t t[DREG];
        #pragma unroll
        for (int r = 0; r < DREG; ++r) t[r] = dense[lane + 32 * r];

        // Bitwise search, skipping the common prefix.
        const uint32_t diff = and_all ^ or_all;
        if (diff == 0) {
            T = and_all;
        } else {
            const int hb = 31 - __clz(diff);
            T = (hb == 31) ? 0u : (and_all & ~((2u << hb) - 1u));
            #pragma unroll 1
            for (int b = hb; b >= 0; --b) {
                const uint32_t c = T | (1u << b);
                int loc = 0;
                #pragma unroll
                for (int r = 0; r < DREG; ++r) loc += (int)(t[r] >= c);
                if (__reduce_add_sync(0xFFFFFFFFu, loc) >= KSEL) T = c;
            }
        }

        // Compact strict survivors via shfl exclusive scan.
        int cg = 0;
        #pragma unroll
        for (int r = 0; r < DREG; ++r) cg += (int)(t[r] > T);
        int so = cg;
        #pragma unroll
        for (int d = 1; d < 32; d <<= 1) {
            int v = __shfl_up_sync(0xFFFFFFFFu, so, d);
            if (lane >= d) so += v;
        }
        total_gt = (uint32_t)__shfl_sync(0xFFFFFFFFu, so, 31);
        so -= cg;  // exclusive
        #pragma unroll
        for (int r = 0; r < DREG; ++r)
            if (t[r] > T) sel[so++] = t[r];
        __syncwarp();
    } else {
        // Exact fallback over the full row (any input distribution).
        const uint32_t* src = reinterpret_cast<const uint32_t*>(x) + (size_t)row * ROW_LEN;
        T = 0;
        #pragma unroll 1
        for (int b = 31; b >= 0; --b) {
            const uint32_t c = T | (1u << b);
            int loc = 0;
            for (int i = lane; i < ROW_LEN; i += 32)
                loc += (int)(fwd_xform(src[i]) >= c);
            if (__reduce_add_sync(0xFFFFFFFFu, loc) >= KSEL) T = c;
        }
        if (lane == 0) fcnt[widx] = 0;
        __syncwarp();
        for (int i = lane; i < ROW_LEN; i += 32) {
            uint32_t u = fwd_xform(src[i]);
            if (u > T) sel[atomicAdd(&fcnt[widx], 1u)] = u;  // < 64 by construction
        }
        __syncwarp();
        total_gt = fcnt[widx];
    }

    // Tie fill + rank-sort 64 winners (descending), write.
    #pragma unroll
    for (int r = 0; r < 2; ++r) {
        int i = lane + 32 * r;
        if ((uint32_t)i >= total_gt) sel[i] = T;
    }
    __syncwarp();

    #pragma unroll
    for (int r = 0; r < 2; ++r) {
        const int i = lane + 32 * r;
        const uint32_t v = sel[i];
        int rank = 0;
        #pragma unroll
        for (int j = 0; j < KSEL; ++j) {
            uint32_t u = sel[j];
            rank += (int)((u > v) | ((u == v) & (j < i)));
        }
        out[(size_t)row * KSEL + rank] = inv_xform(v);
    }
}

extern "C" void kernel_launch(void* const* d_in, const int* in_sizes, int n_in,
                              void* d_out, int out_size) {
    const float* x = (const float*)d_in[0];
    float* out = (float*)d_out;
    int rows = in_sizes[0] / ROW_LEN;
    if (rows > MAXROWS) rows = MAXROWS;
    filter_kernel<<<rows * 2, 256>>>(x);
    select_kernel<<<rows / K2_WARPS, 32 * K2_WARPS>>>(x, out);
}

// round 15
// speedup vs baseline: 1.1513x; 1.0586x over previous
#include <cuda_runtime.h>
#include <cstdint>

#define ROW_LEN   16384
#define KSEL      64
#define MAXROWS   8192
#define UNITS_PER_ROW 16          // 2 CTAs/row x 8 warps in K1
#define SEG       48              // candidate slots per warp-unit
#define T0F       2.30f           // filter threshold; exact fallback covers any input
#define K2_WARPS  4
#define DCAP      256             // dense candidate capacity (8 regs/lane)
#define DREG      8

// Global scratch (static — no allocations).
__device__ uint32_t g_cnt[MAXROWS * UNITS_PER_ROW];
__device__ uint32_t g_seg[MAXROWS * UNITS_PER_ROW * SEG];   // ~25 MB (L2-resident)

// Monotonic transform: descending float order == descending uint order.
__device__ __forceinline__ uint32_t fwd_xform(uint32_t u) {
    return (u & 0x80000000u) ? ~u : (u | 0x80000000u);
}
__device__ __forceinline__ float inv_xform(uint32_t u) {
    return __uint_as_float((u & 0x80000000u) ? (u ^ 0x80000000u) : ~u);
}

// ---------------------------------------------------------------------------
// K1: pure streaming filter, fully warp-independent. One CTA per half-row;
// each warp owns one 1024-element unit (256 float4s, 8 per lane). Ballot-scan
// push straight to gmem: no atomics, no shared memory, no barriers.
// Proven ~78.5 us (~6.85 TB/s). Unchanged.
// ---------------------------------------------------------------------------
__global__ void __launch_bounds__(256, 5)
filter_kernel(const float* __restrict__ x) {
    const int cta  = blockIdx.x;
    const int tid  = threadIdx.x;
    const int wid  = tid >> 5;
    const int lane = tid & 31;

    const uint32_t unit = (uint32_t)cta * 8 + wid;
    uint32_t* seg = g_seg + (size_t)unit * SEG;
    const uint32_t lmask = (1u << lane) - 1u;

    const float4* src4 = reinterpret_cast<const float4*>(x)
                       + (size_t)cta * 2048 + wid * 256 + lane;

    float4 v[8];
    #pragma unroll
    for (int j = 0; j < 8; ++j)
        v[j] = __ldcs(&src4[j * 32]);

    uint32_t cnt = 0;
    #pragma unroll
    for (int j = 0; j < 8; ++j) {
        float f[4] = {v[j].x, v[j].y, v[j].z, v[j].w};
        #pragma unroll
        for (int c = 0; c < 4; ++c) {
            bool p = f[c] > T0F;
            unsigned m = __ballot_sync(0xFFFFFFFFu, p);
            uint32_t pos = cnt + (uint32_t)__popc(m & lmask);
            if (p && pos < SEG) seg[pos] = __float_as_uint(f[c]);
            cnt += (uint32_t)__popc(m);
        }
    }

    if (lane == 0) g_cnt[unit] = cnt;   // cnt > SEG routes K2 to exact fallback
}

// ---------------------------------------------------------------------------
// K2: one WARP per row. Dense-compacted candidates + prefix-skipped exact
// bitwise select + warp bitonic output sort (replaces O(64^2) rank-sort).
// ---------------------------------------------------------------------------
__global__ void __launch_bounds__(32 * K2_WARPS)
select_kernel(const float* __restrict__ x, float* __restrict__ out) {
    __shared__ uint32_t dense_all[K2_WARPS][DCAP];
    __shared__ uint32_t sel_all[K2_WARPS][KSEL];
    __shared__ uint32_t fcnt[K2_WARPS];

    const int widx = threadIdx.x >> 5;
    const int lane = threadIdx.x & 31;
    const int row  = blockIdx.x * K2_WARPS + widx;

    uint32_t* dense = dense_all[widx];
    uint32_t* sel   = sel_all[widx];

    uint32_t myc = (lane < UNITS_PER_ROW) ? g_cnt[row * UNITS_PER_ROW + lane] : 0u;
    const uint32_t total = __reduce_add_sync(0xFFFFFFFFu, myc);
    const bool ovf = __any_sync(0xFFFFFFFFu, myc > SEG);
    const bool fb  = ovf || (total < KSEL) || (total > DCAP);

    uint32_t T;          // transformed bit pattern of the 64th largest
    uint32_t total_gt;   // # strictly greater than T (<= 63)

    if (!fb) {
        // Exclusive prefix of unit counts (lanes >=16 contribute 0).
        uint32_t off = myc;
        #pragma unroll
        for (int d = 1; d < 32; d <<= 1) {
            uint32_t v = __shfl_up_sync(0xFFFFFFFFu, off, d);
            if (lane >= d) off += v;
        }
        const uint32_t excl_me = off - myc;

        // Compact into dense[0..total) (2 lanes per unit). No zero-fill:
        // reads beyond total are discarded by the bounds-select below.
        const int unit = lane >> 1;
        const int sub  = lane & 1;
        const uint32_t cu   = __shfl_sync(0xFFFFFFFFu, myc, unit);
        const uint32_t base = __shfl_sync(0xFFFFFFFFu, excl_me, unit);
        const uint32_t* segp = g_seg + ((size_t)row * UNITS_PER_ROW + unit) * SEG;

        uint32_t land = 0xFFFFFFFFu, lor = 0;  // AND/OR over real candidates
        for (uint32_t j = sub; j < cu; j += 2) {
            uint32_t v = segp[j] | 0x80000000u;   // transformed (all positive)
            dense[base + j] = v;
            land &= v; lor |= v;
        }
        const uint32_t and_all = __reduce_and_sync(0xFFFFFFFFu, land);
        const uint32_t or_all  = __reduce_or_sync(0xFFFFFFFFu, lor);
        __syncwarp();

        uint32_t t[DREG];
        #pragma unroll
        for (int r = 0; r < DREG; ++r) {
            const uint32_t idx = (uint32_t)lane + 32u * r;
            t[r] = (idx < total) ? dense[idx] : 0u;
        }

        // Bitwise search, skipping the common prefix.
        const uint32_t diff = and_all ^ or_all;
        if (diff == 0) {
            T = and_all;
        } else {
            const int hb = 31 - __clz(diff);
            T = (hb == 31) ? 0u : (and_all & ~((2u << hb) - 1u));
            #pragma unroll 1
            for (int b = hb; b >= 0; --b) {
                const uint32_t c = T | (1u << b);
                int loc = 0;
                #pragma unroll
                for (int r = 0; r < DREG; ++r) loc += (int)(t[r] >= c);
                if (__reduce_add_sync(0xFFFFFFFFu, loc) >= KSEL) T = c;
            }
        }

        // Compact strict survivors via shfl exclusive scan.
        int cg = 0;
        #pragma unroll
        for (int r = 0; r < DREG; ++r) cg += (int)(t[r] > T);
        int so = cg;
        #pragma unroll
        for (int d = 1; d < 32; d <<= 1) {
            int v = __shfl_up_sync(0xFFFFFFFFu, so, d);
            if (lane >= d) so += v;
        }
        total_gt = (uint32_t)__shfl_sync(0xFFFFFFFFu, so, 31);
        so -= cg;  // exclusive
        #pragma unroll
        for (int r = 0; r < DREG; ++r)
            if (t[r] > T) sel[so++] = t[r];
        __syncwarp();
    } else {
        // Exact fallback over the full row (any input distribution).
        const uint32_t* src = reinterpret_cast<const uint32_t*>(x) + (size_t)row * ROW_LEN;
        T = 0;
        #pragma unroll 1
        for (int b = 31; b >= 0; --b) {
            const uint32_t c = T | (1u << b);
            int loc = 0;
            for (int i = lane; i < ROW_LEN; i += 32)
                loc += (int)(fwd_xform(src[i]) >= c);
            if (__reduce_add_sync(0xFFFFFFFFu, loc) >= KSEL) T = c;
        }
        if (lane == 0) fcnt[widx] = 0;
        __syncwarp();
        for (int i = lane; i < ROW_LEN; i += 32) {
            uint32_t u = fwd_xform(src[i]);
            if (u > T) sel[atomicAdd(&fcnt[widx], 1u)] = u;  // < 64 by construction
        }
        __syncwarp();
        total_gt = fcnt[widx];
    }

    // ---- Register tie-fill + descending bitonic sort of 64 (2 regs/lane) ----
    // Virtual index i = lane + 32*r.
    uint32_t a = ((uint32_t)lane      < total_gt) ? sel[lane]      : T;
    uint32_t b = ((uint32_t)lane + 32 < total_gt) ? sel[lane + 32] : T;

    #pragma unroll
    for (int k = 2; k <= 64; k <<= 1) {
        #pragma unroll
        for (int j = k >> 1; j > 0; j >>= 1) {
            if (j == 32) {
                // Partner is the other register within the lane (k == 64 here,
                // i & k == 0 for both) -> lower index keeps max.
                uint32_t mx = a > b ? a : b;
                uint32_t mn = a > b ? b : a;
                a = mx; b = mn;
            } else {
                {
                    const int i = lane;
                    uint32_t p = __shfl_xor_sync(0xFFFFFFFFu, a, j);
                    bool keep_max = ((i & j) == 0) ^ ((i & k) != 0);
                    a = keep_max ? (a > p ? a : p) : (a < p ? a : p);
                }
                {
                    const int i = lane + 32;
                    uint32_t p = __shfl_xor_sync(0xFFFFFFFFu, b, j);
                    bool keep_max = ((i & j) == 0) ^ ((i & k) != 0);
                    b = keep_max ? (b > p ? b : p) : (b < p ? b : p);
                }
            }
        }
    }

    // Sorted descending: position i = lane (+32). Coalesced direct store.
    out[(size_t)row * KSEL + lane]      = inv_xform(a);
    out[(size_t)row * KSEL + lane + 32] = inv_xform(b);
}

extern "C" void kernel_launch(void* const* d_in, const int* in_sizes, int n_in,
                              void* d_out, int out_size) {
    const float* x = (const float*)d_in[0];
    float* out = (float*)d_out;
    int rows = in_sizes[0] / ROW_LEN;
    if (rows > MAXROWS) rows = MAXROWS;
    filter_kernel<<<rows * 2, 256>>>(x);
    select_kernel<<<rows / K2_WARPS, 32 * K2_WARPS>>>(x, out);
}

// round 16
// speedup vs baseline: 1.2062x; 1.0477x over previous
#include <cuda_runtime.h>
#include <cstdint>

#define ROW_LEN   16384
#define KSEL      64
#define MAXROWS   8192
#define UNITS_PER_ROW 16          // 2 CTAs/row x 8 warps in K1
#define SEG       48              // candidate slots per warp-unit
#define T0F       2.30f           // filter threshold; exact fallback covers any input
#define K2_WARPS  4
#define DCAP      256             // dense candidate capacity (8 regs/lane)
#define DREG      8

// Global scratch (static — no allocations).
__device__ uint32_t g_cnt[MAXROWS * UNITS_PER_ROW];
__device__ uint32_t g_seg[MAXROWS * UNITS_PER_ROW * SEG];   // ~25 MB (L2-resident)

// Monotonic transform: descending float order == descending uint order.
__device__ __forceinline__ uint32_t fwd_xform(uint32_t u) {
    return (u & 0x80000000u) ? ~u : (u | 0x80000000u);
}
__device__ __forceinline__ float inv_xform(uint32_t u) {
    return __uint_as_float((u & 0x80000000u) ? (u ^ 0x80000000u) : ~u);
}

// ---------------------------------------------------------------------------
// K1: pure streaming filter, fully warp-independent. One CTA per half-row;
// each warp owns one 1024-element unit (256 float4s, 8 per lane). Ballot-scan
// push straight to gmem: no atomics, no shared memory, no barriers.
// Proven ~78 us (~6.85 TB/s). Unchanged.
// ---------------------------------------------------------------------------
__global__ void __launch_bounds__(256, 5)
filter_kernel(const float* __restrict__ x) {
    const int cta  = blockIdx.x;
    const int tid  = threadIdx.x;
    const int wid  = tid >> 5;
    const int lane = tid & 31;

    const uint32_t unit = (uint32_t)cta * 8 + wid;
    uint32_t* seg = g_seg + (size_t)unit * SEG;
    const uint32_t lmask = (1u << lane) - 1u;

    const float4* src4 = reinterpret_cast<const float4*>(x)
                       + (size_t)cta * 2048 + wid * 256 + lane;

    float4 v[8];
    #pragma unroll
    for (int j = 0; j < 8; ++j)
        v[j] = __ldcs(&src4[j * 32]);

    uint32_t cnt = 0;
    #pragma unroll
    for (int j = 0; j < 8; ++j) {
        float f[4] = {v[j].x, v[j].y, v[j].z, v[j].w};
        #pragma unroll
        for (int c = 0; c < 4; ++c) {
            bool p = f[c] > T0F;
            unsigned m = __ballot_sync(0xFFFFFFFFu, p);
            uint32_t pos = cnt + (uint32_t)__popc(m & lmask);
            if (p && pos < SEG) seg[pos] = __float_as_uint(f[c]);
            cnt += (uint32_t)__popc(m);
        }
    }

    if (lane == 0) g_cnt[unit] = cnt;   // cnt > SEG routes K2 to exact fallback
}

// ---------------------------------------------------------------------------
// K2: one WARP per row. Dense-compacted candidates + prefix-skipped exact
// bitwise select with exact-count early exit + warp bitonic output sort.
// ---------------------------------------------------------------------------
__global__ void __launch_bounds__(32 * K2_WARPS)
select_kernel(const float* __restrict__ x, float* __restrict__ out) {
    __shared__ uint32_t dense_all[K2_WARPS][DCAP];
    __shared__ uint32_t sel_all[K2_WARPS][KSEL];
    __shared__ uint32_t fcnt[K2_WARPS];

    const int widx = threadIdx.x >> 5;
    const int lane = threadIdx.x & 31;
    const int row  = blockIdx.x * K2_WARPS + widx;

    uint32_t* dense = dense_all[widx];
    uint32_t* sel   = sel_all[widx];

    uint32_t myc = (lane < UNITS_PER_ROW) ? g_cnt[row * UNITS_PER_ROW + lane] : 0u;
    const uint32_t total = __reduce_add_sync(0xFFFFFFFFu, myc);
    const bool ovf = __any_sync(0xFFFFFFFFu, myc > SEG);
    const bool fb  = ovf || (total < KSEL) || (total > DCAP);

    uint32_t T;          // transformed bit pattern of the 64th largest
    uint32_t total_gt;   // # strictly greater than T (<= 63)

    if (!fb) {
        // Exclusive prefix of unit counts (lanes >=16 contribute 0).
        uint32_t off = myc;
        #pragma unroll
        for (int d = 1; d < 32; d <<= 1) {
            uint32_t v = __shfl_up_sync(0xFFFFFFFFu, off, d);
            if (lane >= d) off += v;
        }
        const uint32_t excl_me = off - myc;

        // Compact into dense[0..total) (2 lanes per unit).
        const int unit = lane >> 1;
        const int sub  = lane & 1;
        const uint32_t cu   = __shfl_sync(0xFFFFFFFFu, myc, unit);
        const uint32_t base = __shfl_sync(0xFFFFFFFFu, excl_me, unit);
        const uint32_t* segp = g_seg + ((size_t)row * UNITS_PER_ROW + unit) * SEG;

        uint32_t land = 0xFFFFFFFFu, lor = 0;  // AND/OR over real candidates
        for (uint32_t j = sub; j < cu; j += 2) {
            uint32_t v = segp[j] | 0x80000000u;   // transformed (all positive)
            dense[base + j] = v;
            land &= v; lor |= v;
        }
        const uint32_t and_all = __reduce_and_sync(0xFFFFFFFFu, land);
        const uint32_t or_all  = __reduce_or_sync(0xFFFFFFFFu, lor);
        __syncwarp();

        uint32_t t[DREG];
        #pragma unroll
        for (int r = 0; r < DREG; ++r) {
            const uint32_t idx = (uint32_t)lane + 32u * r;
            t[r] = (idx < total) ? dense[idx] : 0u;
        }

        // Bitwise search, skipping the common prefix, with exact-count early
        // exit: when #{x >= c} == KSEL, the KSEL-th largest is min{x >= c}.
        const uint32_t diff = and_all ^ or_all;
        if (diff == 0) {
            T = and_all;
        } else {
            const int hb = 31 - __clz(diff);
            T = (hb == 31) ? 0u : (and_all & ~((2u << hb) - 1u));
            #pragma unroll 1
            for (int b = hb; b >= 0; --b) {
                const uint32_t c = T | (1u << b);
                int loc = 0;
                #pragma unroll
                for (int r = 0; r < DREG; ++r) loc += (int)(t[r] >= c);
                const int n = __reduce_add_sync(0xFFFFFFFFu, loc);
                if (n >= KSEL) T = c;
                if (n == KSEL) {   // warp-uniform: exact hit, finish with min
                    uint32_t m = 0xFFFFFFFFu;
                    #pragma unroll
                    for (int r = 0; r < DREG; ++r)
                        if (t[r] >= c) m = min(m, t[r]);
                    T = __reduce_min_sync(0xFFFFFFFFu, m);
                    break;
                }
            }
        }

        // Compact strict survivors via shfl exclusive scan.
        int cg = 0;
        #pragma unroll
        for (int r = 0; r < DREG; ++r) cg += (int)(t[r] > T);
        int so = cg;
        #pragma unroll
        for (int d = 1; d < 32; d <<= 1) {
            int v = __shfl_up_sync(0xFFFFFFFFu, so, d);
            if (lane >= d) so += v;
        }
        total_gt = (uint32_t)__shfl_sync(0xFFFFFFFFu, so, 31);
        so -= cg;  // exclusive
        #pragma unroll
        for (int r = 0; r < DREG; ++r)
            if (t[r] > T) sel[so++] = t[r];
        __syncwarp();
    } else {
        // Exact fallback over the full row (any input distribution).
        const uint32_t* src = reinterpret_cast<const uint32_t*>(x) + (size_t)row * ROW_LEN;
        T = 0;
        #pragma unroll 1
        for (int b = 31; b >= 0; --b) {
            const uint32_t c = T | (1u << b);
            int loc = 0;
            for (int i = lane; i < ROW_LEN; i += 32)
                loc += (int)(fwd_xform(src[i]) >= c);
            if (__reduce_add_sync(0xFFFFFFFFu, loc) >= KSEL) T = c;
        }
        if (lane == 0) fcnt[widx] = 0;
        __syncwarp();
        for (int i = lane; i < ROW_LEN; i += 32) {
            uint32_t u = fwd_xform(src[i]);
            if (u > T) sel[atomicAdd(&fcnt[widx], 1u)] = u;  // < 64 by construction
        }
        __syncwarp();
        total_gt = fcnt[widx];
    }

    // ---- Register tie-fill + descending bitonic sort of 64 (2 regs/lane) ----
    uint32_t a = ((uint32_t)lane      < total_gt) ? sel[lane]      : T;
    uint32_t b = ((uint32_t)lane + 32 < total_gt) ? sel[lane + 32] : T;

    #pragma unroll
    for (int k = 2; k <= 64; k <<= 1) {
        #pragma unroll
        for (int j = k >> 1; j > 0; j >>= 1) {
            if (j == 32) {
                uint32_t mx = a > b ? a : b;
                uint32_t mn = a > b ? b : a;
                a = mx; b = mn;
            } else {
                {
                    const int i = lane;
                    uint32_t p = __shfl_xor_sync(0xFFFFFFFFu, a, j);
                    bool keep_max = ((i & j) == 0) ^ ((i & k) != 0);
                    a = keep_max ? (a > p ? a : p) : (a < p ? a : p);
                }
                {
                    const int i = lane + 32;
                    uint32_t p = __shfl_xor_sync(0xFFFFFFFFu, b, j);
                    bool keep_max = ((i & j) == 0) ^ ((i & k) != 0);
                    b = keep_max ? (b > p ? b : p) : (b < p ? b : p);
                }
            }
        }
    }

    out[(size_t)row * KSEL + lane]      = inv_xform(a);
    out[(size_t)row * KSEL + lane + 32] = inv_xform(b);
}

extern "C" void kernel_launch(void* const* d_in, const int* in_sizes, int n_in,
                              void* d_out, int out_size) {
    const float* x = (const float*)d_in[0];
    float* out = (float*)d_out;
    int rows = in_sizes[0] / ROW_LEN;
    if (rows > MAXROWS) rows = MAXROWS;
    filter_kernel<<<rows * 2, 256>>>(x);
    select_kernel<<<rows / K2_WARPS, 32 * K2_WARPS>>>(x, out);
}